// round 12
// baseline (speedup 1.0000x reference)
#include <cuda_runtime.h>
#include <cuda_bf16.h>
#include <cstdint>
#include <math.h>

#define BB 2
#define NTOK 2048
#define DD 512
#define HH 8
#define DHH 64
#define HIDN 2730
#define HID2 1365
#define HID2P 1408     // padded (interleaved/2) width of hs
#define HIDNP 2816     // padded interleaved N for fc1
#define MTOT (BB*NTOK) // 4096
#define QKVN 1536

// ---------------- scratch (static device globals) ---------------------------
__device__ __nv_bfloat16 g_xn_bf [MTOT*DD];
__device__ __nv_bfloat16 g_xn2_bf[MTOT*DD];
__device__ __nv_bfloat16 g_ctx_bf[MTOT*DD];
__device__ __nv_bfloat16 g_qkv_bf[3*MTOT*DD];
__device__ __nv_bfloat16 g_wqkv_bf[QKVN*DD];
__device__ float         g_qkvb  [QKVN];
__device__ __nv_bfloat16 g_wo_bf [DD*DD];
__device__ __nv_bfloat16 g_fc1w_bf[(size_t)HIDNP*DD];   // interleaved h1/h2 rows
__device__ float         g_fc1b  [HIDNP];               // interleaved bias
__device__ __nv_bfloat16 g_fc2w_bf[(size_t)DD*HID2P];
__device__ __nv_bfloat16 g_hs_bf  [(size_t)MTOT*HID2P];
__device__ float g_x1  [MTOT*DD];

// ---------------- base-ISA helpers ------------------------------------------
__device__ __forceinline__ uint32_t smem_to_u32(const void* p) {
    uint32_t a;
    asm("{ .reg .u64 t; cvta.to.shared.u64 t, %1; cvt.u32.u64 %0, t; }"
        : "=r"(a) : "l"(p));
    return a;
}
#define SMEM_SWIZZLE_128B(o) ((o) ^ (((o) >> 3) & 0x70))

__device__ __forceinline__ void cp_async16(uint32_t saddr, const void* gptr) {
    asm volatile("cp.async.cg.shared.global [%0], [%1], 16;"
                 :: "r"(saddr), "l"(gptr));
}
__device__ __forceinline__ void ldmatrix_x4(uint32_t& r0, uint32_t& r1,
                                            uint32_t& r2, uint32_t& r3,
                                            uint32_t addr) {
    asm volatile("ldmatrix.sync.aligned.m8n8.x4.shared.b16 {%0,%1,%2,%3}, [%4];"
                 : "=r"(r0), "=r"(r1), "=r"(r2), "=r"(r3) : "r"(addr));
}
__device__ __forceinline__ void ldmatrix_x4_trans(uint32_t& r0, uint32_t& r1,
                                                  uint32_t& r2, uint32_t& r3,
                                                  uint32_t addr) {
    asm volatile("ldmatrix.sync.aligned.m8n8.x4.trans.shared.b16 {%0,%1,%2,%3}, [%4];"
                 : "=r"(r0), "=r"(r1), "=r"(r2), "=r"(r3) : "r"(addr));
}
__device__ __forceinline__ void mma_bf16(float* c,
                                         uint32_t a0, uint32_t a1, uint32_t a2, uint32_t a3,
                                         uint32_t b0, uint32_t b1) {
    asm volatile(
        "mma.sync.aligned.m16n8k16.row.col.f32.bf16.bf16.f32 "
        "{%0,%1,%2,%3}, {%4,%5,%6,%7}, {%8,%9}, {%0,%1,%2,%3};"
        : "+f"(c[0]), "+f"(c[1]), "+f"(c[2]), "+f"(c[3])
        : "r"(a0), "r"(a1), "r"(a2), "r"(a3), "r"(b0), "r"(b1));
}
__device__ __forceinline__ float ex2f(float x) {
    float r; asm("ex2.approx.f32 %0, %1;" : "=f"(r) : "f"(x)); return r;
}
__device__ __forceinline__ float sqrt_ap(float x) {
    float r; asm("sqrt.approx.f32 %0, %1;" : "=f"(r) : "f"(x)); return r;
}

// ---------------- epilogue helper (shared by both GEMM kernels) -------------
__device__ __forceinline__ void gemm_epilogue(
    int r0, int n0, int Nc, int ldc,
    const float* acc4, const float* __restrict__ bias,
    float* __restrict__ C, __nv_bfloat16* __restrict__ Cb,
    const float* __restrict__ res, const float* __restrict__ gamma, int mode)
{
    if (n0 >= Nc) return;
    float b0 = bias[n0], b1 = bias[n0 + 1];
    float v0 = acc4[0] + b0, v1 = acc4[1] + b1;
    float v2 = acc4[2] + b0, v3 = acc4[3] + b1;
    if (mode == 4) {
        int buf = n0 >> 9, cc = n0 & 511;
        __nv_bfloat16* dst = Cb + (size_t)buf * ((size_t)MTOT * DD)
                                + (size_t)r0 * DD + cc;
        *(__nv_bfloat162*)dst = __floats2bfloat162_rn(v0, v1);
        *(__nv_bfloat162*)(dst + 8 * DD) = __floats2bfloat162_rn(v2, v3);
    } else if (mode == 3) {
        int j = n0 >> 1;
        float s0 = v0 / (1.0f + __expf(-v0));
        float s2 = v2 / (1.0f + __expf(-v2));
        Cb[(size_t)r0 * ldc + j]       = __float2bfloat16(s0 * v1);
        Cb[(size_t)(r0 + 8) * ldc + j] = __float2bfloat16(s2 * v3);
    } else {
        float g0 = gamma[n0], g1 = gamma[n0 + 1];
        v0 = res[(size_t)r0 * ldc + n0]           + g0 * v0;
        v1 = res[(size_t)r0 * ldc + n0 + 1]       + g1 * v1;
        v2 = res[(size_t)(r0 + 8) * ldc + n0]     + g0 * v2;
        v3 = res[(size_t)(r0 + 8) * ldc + n0 + 1] + g1 * v3;
        *(float2*)&C[(size_t)r0 * ldc + n0]       = make_float2(v0, v1);
        *(float2*)&C[(size_t)(r0 + 8) * ldc + n0] = make_float2(v2, v3);
    }
}

// ---------------- bf16 warp-MMA NT GEMM (CTA 128x64, BK=64, 2-stage) --------
// for small-N GEMMs (o-proj, fc2) where grid must stay >= 256 CTAs
__global__ void __launch_bounds__(256) gemm_mma(
    const __nv_bfloat16* __restrict__ A,
    const __nv_bfloat16* __restrict__ Bw,
    const float* __restrict__ bias,
    float* __restrict__ C, __nv_bfloat16* __restrict__ Cb,
    int ldc, int Nc, int K,
    const float* __restrict__ res, const float* __restrict__ gamma, int mode)
{
    extern __shared__ char smem[];
    uint32_t sbase = smem_to_u32(smem);
    const int tid = threadIdx.x, lane = tid & 31, wid = tid >> 5;
    const int wm = wid & 1, wn = wid >> 1;
    const int bm = blockIdx.y * 128, bn = blockIdx.x * 64;

    const uint32_t STAGE = 24576u;
    const uint32_t BOFF  = 16384u;

    float acc[4][2][4];
    #pragma unroll
    for (int i = 0; i < 4; i++)
        #pragma unroll
        for (int j = 0; j < 2; j++)
            #pragma unroll
            for (int t = 0; t < 4; t++) acc[i][j][t] = 0.0f;

    const int lrow = tid >> 3;
    const int lcol = tid & 7;
    const int nch  = K >> 6;

    const int arow  = wm * 64 + (lane & 15);
    const int akoff = lane >> 4;
    const int brow  = wn * 16 + (lane & 7) + ((lane >> 4) << 3);
    const int bkoff = (lane >> 3) & 1;

    auto issue = [&](int c, int s) {
        uint32_t sb = sbase + (uint32_t)s * STAGE;
        #pragma unroll
        for (int i = 0; i < 4; i++) {
            int r = lrow + i * 32;
            uint32_t off = SMEM_SWIZZLE_128B((uint32_t)(r * 128 + lcol * 16));
            cp_async16(sb + off, A + (size_t)(bm + r) * K + c * 64 + lcol * 8);
        }
        #pragma unroll
        for (int i = 0; i < 2; i++) {
            int r = lrow + i * 32;
            uint32_t off = SMEM_SWIZZLE_128B((uint32_t)(r * 128 + lcol * 16));
            cp_async16(sb + BOFF + off, Bw + (size_t)(bn + r) * K + c * 64 + lcol * 8);
        }
        asm volatile("cp.async.commit_group;" ::: "memory");
    };

    issue(0, 0);
    for (int c = 0; c < nch; c++) {
        int s = c & 1;
        if (c + 1 < nch) {
            issue(c + 1, (c + 1) & 1);
            asm volatile("cp.async.wait_group 1;" ::: "memory");
        } else {
            asm volatile("cp.async.wait_group 0;" ::: "memory");
        }
        __syncthreads();

        uint32_t sa  = sbase + (uint32_t)s * STAGE;
        uint32_t sbb = sa + BOFF;
        #pragma unroll
        for (int ks = 0; ks < 4; ks++) {
            uint32_t a[4][4], b[4];
            #pragma unroll
            for (int mi = 0; mi < 4; mi++) {
                int r = arow + mi * 16;
                uint32_t addr = sa + SMEM_SWIZZLE_128B(
                    (uint32_t)(r * 128 + (2 * ks + akoff) * 16));
                ldmatrix_x4(a[mi][0], a[mi][1], a[mi][2], a[mi][3], addr);
            }
            {
                uint32_t addr = sbb + SMEM_SWIZZLE_128B(
                    (uint32_t)(brow * 128 + (2 * ks + bkoff) * 16));
                ldmatrix_x4(b[0], b[1], b[2], b[3], addr);
            }
            #pragma unroll
            for (int mi = 0; mi < 4; mi++) {
                mma_bf16(acc[mi][0], a[mi][0], a[mi][1], a[mi][2], a[mi][3], b[0], b[1]);
                mma_bf16(acc[mi][1], a[mi][0], a[mi][1], a[mi][2], a[mi][3], b[2], b[3]);
            }
        }
        __syncthreads();
    }

    int rbase = bm + wm * 64 + (lane >> 2);
    int cbase = bn + wn * 16 + 2 * (lane & 3);
    #pragma unroll
    for (int mi = 0; mi < 4; mi++)
        #pragma unroll
        for (int ni = 0; ni < 2; ni++)
            gemm_epilogue(rbase + mi * 16, cbase + ni * 8, Nc, ldc,
                          acc[mi][ni], bias, C, Cb, res, gamma, mode);
}

// ---------------- bf16 warp-MMA NT GEMM (CTA 128x128, BK=64, 2-stage) -------
// for big-N GEMMs (qkv N=1536, fc1 N=2816): halves A/B L2 re-read traffic.
__global__ void __launch_bounds__(256) gemm_mma_big(
    const __nv_bfloat16* __restrict__ A,
    const __nv_bfloat16* __restrict__ Bw,
    const float* __restrict__ bias,
    float* __restrict__ C, __nv_bfloat16* __restrict__ Cb,
    int ldc, int Nc, int K,
    const float* __restrict__ res, const float* __restrict__ gamma, int mode)
{
    extern __shared__ char smem[];
    uint32_t sbase = smem_to_u32(smem);
    const int tid = threadIdx.x, lane = tid & 31, wid = tid >> 5;
    const int wm = wid & 1, wn = wid >> 1;
    const int bm = blockIdx.y * 128, bn = blockIdx.x * 128;

    const uint32_t STAGE = 32768u;
    const uint32_t BOFF  = 16384u;

    float acc[4][4][4];
    #pragma unroll
    for (int i = 0; i < 4; i++)
        #pragma unroll
        for (int j = 0; j < 4; j++)
            #pragma unroll
            for (int t = 0; t < 4; t++) acc[i][j][t] = 0.0f;

    const int lrow = tid >> 3;
    const int lcol = tid & 7;
    const int nch  = K >> 6;

    const int arow  = wm * 64 + (lane & 15);
    const int akoff = lane >> 4;
    const int brow  = wn * 32 + (lane & 7) + ((lane >> 4) << 3);
    const int bkoff = (lane >> 3) & 1;

    auto issue = [&](int c, int s) {
        uint32_t sb = sbase + (uint32_t)s * STAGE;
        #pragma unroll
        for (int i = 0; i < 4; i++) {
            int r = lrow + i * 32;
            uint32_t off = SMEM_SWIZZLE_128B((uint32_t)(r * 128 + lcol * 16));
            cp_async16(sb + off,        A  + (size_t)(bm + r) * K + c * 64 + lcol * 8);
            cp_async16(sb + BOFF + off, Bw + (size_t)(bn + r) * K + c * 64 + lcol * 8);
        }
        asm volatile("cp.async.commit_group;" ::: "memory");
    };

    issue(0, 0);
    for (int c = 0; c < nch; c++) {
        int s = c & 1;
        if (c + 1 < nch) {
            issue(c + 1, (c + 1) & 1);
            asm volatile("cp.async.wait_group 1;" ::: "memory");
        } else {
            asm volatile("cp.async.wait_group 0;" ::: "memory");
        }
        __syncthreads();

        uint32_t sa  = sbase + (uint32_t)s * STAGE;
        uint32_t sbb = sa + BOFF;
        #pragma unroll
        for (int ks = 0; ks < 4; ks++) {
            uint32_t a[4][4], b[4][2];
            #pragma unroll
            for (int mi = 0; mi < 4; mi++) {
                int r = arow + mi * 16;
                uint32_t addr = sa + SMEM_SWIZZLE_128B(
                    (uint32_t)(r * 128 + (2 * ks + akoff) * 16));
                ldmatrix_x4(a[mi][0], a[mi][1], a[mi][2], a[mi][3], addr);
            }
            #pragma unroll
            for (int nj = 0; nj < 2; nj++) {
                int r = brow + nj * 16;
                uint32_t addr = sbb + SMEM_SWIZZLE_128B(
                    (uint32_t)(r * 128 + (2 * ks + bkoff) * 16));
                ldmatrix_x4(b[nj*2][0], b[nj*2][1], b[nj*2+1][0], b[nj*2+1][1], addr);
            }
            #pragma unroll
            for (int mi = 0; mi < 4; mi++)
                #pragma unroll
                for (int ni = 0; ni < 4; ni++)
                    mma_bf16(acc[mi][ni], a[mi][0], a[mi][1], a[mi][2], a[mi][3],
                             b[ni][0], b[ni][1]);
        }
        __syncthreads();
    }

    int rbase = bm + wm * 64 + (lane >> 2);
    int cbase = bn + wn * 32 + 2 * (lane & 3);
    #pragma unroll
    for (int mi = 0; mi < 4; mi++)
        #pragma unroll
        for (int ni = 0; ni < 4; ni++)
            gemm_epilogue(rbase + mi * 16, cbase + ni * 8, Nc, ldc,
                          acc[mi][ni], bias, C, Cb, res, gamma, mode);
}

// ---------------- LayerNorm -> bf16 (warp per row) --------------------------
__global__ void __launch_bounds__(128) ln_bf16_kernel(
    const float* __restrict__ x, const float* __restrict__ w,
    const float* __restrict__ b, __nv_bfloat16* __restrict__ out) {
    int warp = threadIdx.x >> 5, lane = threadIdx.x & 31;
    int row = blockIdx.x * 4 + warp;
    const float4* xr = (const float4*)(x + (size_t)row * DD);
    float4 v[4];
    float s = 0.0f, sq = 0.0f;
    #pragma unroll
    for (int i = 0; i < 4; i++) {
        v[i] = xr[lane + 32 * i];
        s  += v[i].x + v[i].y + v[i].z + v[i].w;
        sq += v[i].x*v[i].x + v[i].y*v[i].y + v[i].z*v[i].z + v[i].w*v[i].w;
    }
    #pragma unroll
    for (int o = 16; o; o >>= 1) {
        s  += __shfl_xor_sync(0xffffffffu, s,  o);
        sq += __shfl_xor_sync(0xffffffffu, sq, o);
    }
    float mean = s * (1.0f / DD);
    float var  = sq * (1.0f / DD) - mean * mean;
    float rstd = rsqrtf(var + 1e-5f);
    const float4* wr = (const float4*)w;
    const float4* br = (const float4*)b;
    uint2* orow = (uint2*)(out + (size_t)row * DD);
    #pragma unroll
    for (int i = 0; i < 4; i++) {
        float4 wv = wr[lane + 32 * i];
        float4 bv = br[lane + 32 * i];
        float o0 = (v[i].x - mean) * rstd * wv.x + bv.x;
        float o1 = (v[i].y - mean) * rstd * wv.y + bv.y;
        float o2 = (v[i].z - mean) * rstd * wv.z + bv.z;
        float o3 = (v[i].w - mean) * rstd * wv.w + bv.w;
        __nv_bfloat162 lo = __floats2bfloat162_rn(o0, o1);
        __nv_bfloat162 hi = __floats2bfloat162_rn(o2, o3);
        uint2 u; u.x = *(uint32_t*)&lo; u.y = *(uint32_t*)&hi;
        orow[lane + 32 * i] = u;
    }
}

// ---------------- weight converts -------------------------------------------
__global__ void conv_qkv_kernel(const float* __restrict__ qw, const float* __restrict__ kw,
                                const float* __restrict__ vw, const float* __restrict__ ow,
                                const float* __restrict__ qb, const float* __restrict__ kb,
                                const float* __restrict__ vb2,
                                __nv_bfloat16* __restrict__ wqkv,
                                __nv_bfloat16* __restrict__ wo,
                                float* __restrict__ qkvb) {
    int idx = blockIdx.x * 256 + threadIdx.x;
    if (idx < DD * DD) {
        wqkv[idx]               = __float2bfloat16(qw[idx]);
        wqkv[idx +     DD * DD] = __float2bfloat16(kw[idx]);
        wqkv[idx + 2 * DD * DD] = __float2bfloat16(vw[idx]);
        wo[idx]                 = __float2bfloat16(ow[idx]);
    }
    if (idx < QKVN) {
        float bv = (idx < 512) ? qb[idx] : (idx < 1024) ? kb[idx - 512] : vb2[idx - 1024];
        qkvb[idx] = bv;
    }
}
// fc1 interleave, vectorized 4 elems/thread
__global__ void conv_fc1_kernel(const float* __restrict__ src, const float* __restrict__ bias,
                                __nv_bfloat16* __restrict__ dst, float* __restrict__ bdst) {
    int idx = blockIdx.x * 256 + threadIdx.x;
    int total = HIDNP * (DD / 4);
    if (idx < total) {
        int r  = idx / (DD / 4);
        int c4 = idx - r * (DD / 4);
        int j = r >> 1, half = r & 1;
        float4 v = make_float4(0.f, 0.f, 0.f, 0.f);
        if (j < HID2)
            v = *(const float4*)&src[(size_t)(j + half * HID2) * DD + c4 * 4];
        __nv_bfloat162 lo = __floats2bfloat162_rn(v.x, v.y);
        __nv_bfloat162 hi = __floats2bfloat162_rn(v.z, v.w);
        uint2 u; u.x = *(uint32_t*)&lo; u.y = *(uint32_t*)&hi;
        *(uint2*)&dst[(size_t)r * DD + c4 * 4] = u;
    }
    if (idx < HIDNP) {
        int j = idx >> 1, half = idx & 1;
        bdst[idx] = (j < HID2) ? bias[j + half * HID2] : 0.0f;
    }
}
__global__ void conv_fc2_kernel(const float* __restrict__ src, __nv_bfloat16* __restrict__ dst) {
    size_t idx = (size_t)blockIdx.x * 256 + threadIdx.x;
    if (idx >= (size_t)DD * HID2P) return;
    int n = (int)(idx / HID2P);
    int k = (int)(idx - (size_t)n * HID2P);
    float v = (k < HID2) ? src[(size_t)n * HID2 + k] : 0.0f;
    dst[idx] = __float2bfloat16(v);
}

// ---------------- FA2 warp-MMA attention (128 queries/CTA, 8 warps) ---------
__global__ void __launch_bounds__(256) attn_mma(
    const __nv_bfloat16* __restrict__ q, const __nv_bfloat16* __restrict__ k,
    const __nv_bfloat16* __restrict__ vb, const float* __restrict__ coords,
    __nv_bfloat16* __restrict__ ctx)
{
    const int b = blockIdx.z, h = blockIdx.y, qt = blockIdx.x;
    const int tid = threadIdx.x, lane = tid & 31, wid = tid >> 5;

    __shared__ __align__(128) __nv_bfloat16 Ksm[2][64 * 64];
    __shared__ __align__(128) __nv_bfloat16 Vsm[2][64 * 64];
    __shared__ __align__(16) float2 Kc[2][64];

    const float LOG2E = 1.4426950408889634f;
    const float qscale = 0.125f * LOG2E;
    const float slope2 = exp2f(-(float)(h + 1)) * LOG2E;

    const int r0 = lane >> 2;
    const int gq0 = b * NTOK + qt * 128 + wid * 16 + r0;
    const int c0base = 2 * (lane & 3);

    uint32_t a[4][4];
    {
        const __nv_bfloat16* qp0 = q + (size_t)gq0 * DD + h * DHH;
        const __nv_bfloat16* qp1 = qp0 + 8 * DD;
        #pragma unroll
        for (int kt = 0; kt < 4; kt++) {
            a[kt][0] = *(const uint32_t*)(qp0 + kt * 16 + c0base);
            a[kt][1] = *(const uint32_t*)(qp1 + kt * 16 + c0base);
            a[kt][2] = *(const uint32_t*)(qp0 + kt * 16 + c0base + 8);
            a[kt][3] = *(const uint32_t*)(qp1 + kt * 16 + c0base + 8);
        }
    }
    float qx0 = coords[(size_t)gq0 * 2],       qy0 = coords[(size_t)gq0 * 2 + 1];
    float qx1 = coords[(size_t)(gq0 + 8) * 2], qy1 = coords[(size_t)(gq0 + 8) * 2 + 1];

    float o[8][4];
    #pragma unroll
    for (int j = 0; j < 8; j++)
        #pragma unroll
        for (int t = 0; t < 4; t++) o[j][t] = 0.0f;
    float m0 = -1e30f, m1 = -1e30f, l0 = 0.0f, l1 = 0.0f;

    uint32_t ksm_u = smem_to_u32(Ksm);
    uint32_t vsm_u = smem_to_u32(Vsm);
    uint32_t kc_u  = smem_to_u32(Kc);

    const int lr = tid >> 2, lq = tid & 3;
    const int brow = (lane & 7) + ((lane >> 4) << 3);
    const int bkoff = (lane >> 3) & 1;

    auto issue = [&](int kb, int s) {
        const __nv_bfloat16* kg = k  + (size_t)(b * NTOK + kb + lr) * DD + h * DHH + lq * 16;
        const __nv_bfloat16* vg = vb + (size_t)(b * NTOK + kb + lr) * DD + h * DHH + lq * 16;
        uint32_t o0 = SMEM_SWIZZLE_128B((uint32_t)(lr * 128 + lq * 32));
        uint32_t o1 = SMEM_SWIZZLE_128B((uint32_t)(lr * 128 + lq * 32 + 16));
        cp_async16(ksm_u + (uint32_t)s * 8192u + o0, kg);
        cp_async16(ksm_u + (uint32_t)s * 8192u + o1, kg + 8);
        cp_async16(vsm_u + (uint32_t)s * 8192u + o0, vg);
        cp_async16(vsm_u + (uint32_t)s * 8192u + o1, vg + 8);
        if (tid < 32) {
            cp_async16(kc_u + (uint32_t)s * 512u + (uint32_t)tid * 16u,
                       coords + (size_t)(b * NTOK + kb) * 2 + tid * 4);
        }
        asm volatile("cp.async.commit_group;" ::: "memory");
    };

    issue(0, 0);
    const int ntiles = NTOK / 64;
    for (int c = 0; c < ntiles; c++) {
        int s = c & 1;
        if (c + 1 < ntiles) {
            issue((c + 1) * 64, s ^ 1);
            asm volatile("cp.async.wait_group 1;" ::: "memory");
        } else {
            asm volatile("cp.async.wait_group 0;" ::: "memory");
        }
        __syncthreads();

        float sacc[8][4];
        #pragma unroll
        for (int j = 0; j < 8; j++)
            #pragma unroll
            for (int t = 0; t < 4; t++) sacc[j][t] = 0.0f;
        uint32_t kbase = ksm_u + (uint32_t)s * 8192u;
        #pragma unroll
        for (int ks = 0; ks < 4; ks++) {
            #pragma unroll
            for (int jj = 0; jj < 4; jj++) {
                uint32_t addr = kbase + SMEM_SWIZZLE_128B(
                    (uint32_t)((jj * 16 + brow) * 128 + (2 * ks + bkoff) * 16));
                uint32_t b0, b1, b2, b3;
                ldmatrix_x4(b0, b1, b2, b3, addr);
                mma_bf16(sacc[2 * jj],     a[ks][0], a[ks][1], a[ks][2], a[ks][3], b0, b1);
                mma_bf16(sacc[2 * jj + 1], a[ks][0], a[ks][1], a[ks][2], a[ks][3], b2, b3);
            }
        }

        float tm0 = -1e30f, tm1 = -1e30f;
        #pragma unroll
        for (int j = 0; j < 8; j++) {
            int cc = 8 * j + c0base;
            float2 k0 = Kc[s][cc], k1 = Kc[s][cc + 1];
            float dxa = qx0 - k0.x, dya = qy0 - k0.y;
            float dxb = qx0 - k1.x, dyb = qy0 - k1.y;
            float dxc = qx1 - k0.x, dyc = qy1 - k0.y;
            float dxd = qx1 - k1.x, dyd = qy1 - k1.y;
            sacc[j][0] = fmaf(sacc[j][0], qscale, -slope2 * sqrt_ap(dxa * dxa + dya * dya));
            sacc[j][1] = fmaf(sacc[j][1], qscale, -slope2 * sqrt_ap(dxb * dxb + dyb * dyb));
            sacc[j][2] = fmaf(sacc[j][2], qscale, -slope2 * sqrt_ap(dxc * dxc + dyc * dyc));
            sacc[j][3] = fmaf(sacc[j][3], qscale, -slope2 * sqrt_ap(dxd * dxd + dyd * dyd));
            tm0 = fmaxf(tm0, fmaxf(sacc[j][0], sacc[j][1]));
            tm1 = fmaxf(tm1, fmaxf(sacc[j][2], sacc[j][3]));
        }
        #pragma unroll
        for (int off = 1; off <= 2; off <<= 1) {
            tm0 = fmaxf(tm0, __shfl_xor_sync(0xffffffffu, tm0, off));
            tm1 = fmaxf(tm1, __shfl_xor_sync(0xffffffffu, tm1, off));
        }

        float mn0 = fmaxf(m0, tm0), mn1 = fmaxf(m1, tm1);
        float cr0 = ex2f(m0 - mn0), cr1 = ex2f(m1 - mn1);
        m0 = mn0; m1 = mn1;
        l0 *= cr0; l1 *= cr1;
        #pragma unroll
        for (int j = 0; j < 8; j++) {
            o[j][0] *= cr0; o[j][1] *= cr0;
            o[j][2] *= cr1; o[j][3] *= cr1;
        }
        #pragma unroll
        for (int j = 0; j < 8; j++) {
            float p0 = ex2f(sacc[j][0] - m0);
            float p1 = ex2f(sacc[j][1] - m0);
            float p2 = ex2f(sacc[j][2] - m1);
            float p3 = ex2f(sacc[j][3] - m1);
            l0 += p0 + p1; l1 += p2 + p3;
            sacc[j][0] = p0; sacc[j][1] = p1; sacc[j][2] = p2; sacc[j][3] = p3;
        }

        uint32_t vbase = vsm_u + (uint32_t)s * 8192u;
        #pragma unroll
        for (int t = 0; t < 4; t++) {
            __nv_bfloat162 h0 = __floats2bfloat162_rn(sacc[2*t][0],   sacc[2*t][1]);
            __nv_bfloat162 h1 = __floats2bfloat162_rn(sacc[2*t][2],   sacc[2*t][3]);
            __nv_bfloat162 h2 = __floats2bfloat162_rn(sacc[2*t+1][0], sacc[2*t+1][1]);
            __nv_bfloat162 h3 = __floats2bfloat162_rn(sacc[2*t+1][2], sacc[2*t+1][3]);
            uint32_t pa0 = *(uint32_t*)&h0, pa1 = *(uint32_t*)&h1;
            uint32_t pa2 = *(uint32_t*)&h2, pa3 = *(uint32_t*)&h3;
            #pragma unroll
            for (int g = 0; g < 4; g++) {
                uint32_t addr = vbase + SMEM_SWIZZLE_128B(
                    (uint32_t)((16 * t + (lane & 15)) * 128 + (16 * g + 8 * (lane >> 4)) * 2));
                uint32_t b0, b1, b2, b3;
                ldmatrix_x4_trans(b0, b1, b2, b3, addr);
                mma_bf16(o[2 * g],     pa0, pa1, pa2, pa3, b0, b1);
                mma_bf16(o[2 * g + 1], pa0, pa1, pa2, pa3, b2, b3);
            }
        }
        __syncthreads();
    }

    #pragma unroll
    for (int off = 1; off <= 2; off <<= 1) {
        l0 += __shfl_xor_sync(0xffffffffu, l0, off);
        l1 += __shfl_xor_sync(0xffffffffu, l1, off);
    }
    float inv0 = 1.0f / l0, inv1 = 1.0f / l1;
    __nv_bfloat16* crow0 = ctx + (size_t)gq0 * DD + h * DHH;
    __nv_bfloat16* crow1 = crow0 + 8 * DD;
    #pragma unroll
    for (int j = 0; j < 8; j++) {
        int d = 8 * j + c0base;
        *(__nv_bfloat162*)(crow0 + d) = __floats2bfloat162_rn(o[j][0] * inv0, o[j][1] * inv0);
        *(__nv_bfloat162*)(crow1 + d) = __floats2bfloat162_rn(o[j][2] * inv1, o[j][3] * inv1);
    }
}

// ---------------- launcher --------------------------------------------------
extern "C" void kernel_launch(void* const* d_in, const int* in_sizes, int n_in,
                              void* d_out, int out_size) {
    (void)in_sizes; (void)n_in; (void)out_size;
    const float* x      = (const float*)d_in[0];
    const float* coords = (const float*)d_in[1];
    const float* q_w    = (const float*)d_in[2];
    const float* q_b    = (const float*)d_in[3];
    const float* k_w    = (const float*)d_in[4];
    const float* k_b    = (const float*)d_in[5];
    const float* v_w    = (const float*)d_in[6];
    const float* v_b    = (const float*)d_in[7];
    const float* o_w    = (const float*)d_in[8];
    const float* o_b    = (const float*)d_in[9];
    const float* gamma1 = (const float*)d_in[10];
    const float* ln1_w  = (const float*)d_in[11];
    const float* ln1_b  = (const float*)d_in[12];
    const float* fc1_w  = (const float*)d_in[13];
    const float* fc1_b  = (const float*)d_in[14];
    const float* fc2_w  = (const float*)d_in[15];
    const float* fc2_b  = (const float*)d_in[16];
    const float* gamma2 = (const float*)d_in[17];
    const float* ln2_w  = (const float*)d_in[18];
    const float* ln2_b  = (const float*)d_in[19];
    float* out = (float*)d_out;

    __nv_bfloat16 *xn, *xn2, *ctxb, *qkv, *wqkv, *wo, *fc1w, *fc2w, *hsb;
    float *x1, *qkvb, *fc1b;
    cudaGetSymbolAddress((void**)&xn,   g_xn_bf);
    cudaGetSymbolAddress((void**)&xn2,  g_xn2_bf);
    cudaGetSymbolAddress((void**)&ctxb, g_ctx_bf);
    cudaGetSymbolAddress((void**)&qkv,  g_qkv_bf);
    cudaGetSymbolAddress((void**)&wqkv, g_wqkv_bf);
    cudaGetSymbolAddress((void**)&wo,   g_wo_bf);
    cudaGetSymbolAddress((void**)&fc1w, g_fc1w_bf);
    cudaGetSymbolAddress((void**)&fc2w, g_fc2w_bf);
    cudaGetSymbolAddress((void**)&hsb,  g_hs_bf);
    cudaGetSymbolAddress((void**)&x1,   g_x1);
    cudaGetSymbolAddress((void**)&qkvb, g_qkvb);
    cudaGetSymbolAddress((void**)&fc1b, g_fc1b);

    const int SMEM_GEMM  = 49152;
    const int SMEM_GEMMB = 65536;
    // Unconditional host-side attribute set (proven container-safe in R10).
    cudaFuncSetAttribute(gemm_mma_big, cudaFuncAttributeMaxDynamicSharedMemorySize, SMEM_GEMMB);

    // weight conversions
    conv_qkv_kernel<<<(DD * DD + 255) / 256, 256>>>(q_w, k_w, v_w, o_w, q_b, k_b, v_b,
                                                    wqkv, wo, qkvb);
    {
        int n2 = HIDNP * (DD / 4);
        conv_fc1_kernel<<<(n2 + 255) / 256, 256>>>(fc1_w, fc1_b, fc1w, fc1b);
        size_t n3 = (size_t)DD * HID2P;
        conv_fc2_kernel<<<(int)((n3 + 255) / 256), 256>>>(fc2_w, fc2w);
    }

    ln_bf16_kernel<<<MTOT / 4, 128>>>(x, ln1_w, ln1_b, xn);

    // fused QKV projection (128x128 tile; grid 12x32 = 384 CTAs)
    dim3 gqkv(QKVN / 128, MTOT / 128);
    gemm_mma_big<<<gqkv, 256, SMEM_GEMMB>>>(xn, wqkv, qkvb, nullptr, qkv, DD, QKVN, DD,
                                            nullptr, nullptr, 4);

    // FA2 attention (128 queries/CTA)
    dim3 gattn(NTOK / 128, HH, BB);
    attn_mma<<<gattn, 256>>>(qkv, qkv + (size_t)MTOT * DD, qkv + 2 * (size_t)MTOT * DD,
                             coords, ctxb);

    // O projection + residual1 (128x64 tile; grid 8x32 = 256 CTAs)
    dim3 gproj(DD / 64, MTOT / 128);
    gemm_mma<<<gproj, 256, SMEM_GEMM>>>(ctxb, wo, o_b, x1, nullptr, DD, DD, DD, x, gamma1, 1);

    ln_bf16_kernel<<<MTOT / 4, 128>>>(x1, ln2_w, ln2_b, xn2);

    // fc1 + fused SwiGLU (128x128 tile; grid 22x32 = 704 CTAs)
    dim3 gfc1(HIDNP / 128, MTOT / 128);
    gemm_mma_big<<<gfc1, 256, SMEM_GEMMB>>>(xn2, fc1w, fc1b, nullptr, hsb, HID2P, HIDNP, DD,
                                            nullptr, nullptr, 3);

    // fc2 + residual2 -> out (128x64 tile)
    gemm_mma<<<gproj, 256, SMEM_GEMM>>>(hsb, fc2w, fc2_b, out, nullptr, DD, DD, HID2P,
                                        x1, gamma2, 1);
}

// round 13
// speedup vs baseline: 1.0735x; 1.0735x over previous
#include <cuda_runtime.h>
#include <cuda_bf16.h>
#include <cstdint>
#include <math.h>

#define BB 2
#define NTOK 2048
#define DD 512
#define HH 8
#define DHH 64
#define HIDN 2730
#define HID2 1365
#define HID2P 1408     // padded (interleaved/2) width of hs
#define HIDNP 2816     // padded interleaved N for fc1
#define MTOT (BB*NTOK) // 4096
#define QKVN 1536

// ---------------- scratch (static device globals) ---------------------------
__device__ __nv_bfloat16 g_xn_bf [MTOT*DD];
__device__ __nv_bfloat16 g_xn2_bf[MTOT*DD];
__device__ __nv_bfloat16 g_ctx_bf[MTOT*DD];
__device__ __nv_bfloat16 g_qkv_bf[3*MTOT*DD];
__device__ __nv_bfloat16 g_wqkv_bf[QKVN*DD];
__device__ float         g_qkvb  [QKVN];
__device__ __nv_bfloat16 g_wo_bf [DD*DD];
__device__ __nv_bfloat16 g_fc1w_bf[(size_t)HIDNP*DD];   // interleaved h1/h2 rows
__device__ float         g_fc1b  [HIDNP];               // interleaved bias
__device__ __nv_bfloat16 g_fc2w_bf[(size_t)DD*HID2P];
__device__ __nv_bfloat16 g_hs_bf  [(size_t)MTOT*HID2P];
__device__ float g_x1  [MTOT*DD];

// ---------------- base-ISA helpers ------------------------------------------
__device__ __forceinline__ uint32_t smem_to_u32(const void* p) {
    uint32_t a;
    asm("{ .reg .u64 t; cvta.to.shared.u64 t, %1; cvt.u32.u64 %0, t; }"
        : "=r"(a) : "l"(p));
    return a;
}
#define SMEM_SWIZZLE_128B(o) ((o) ^ (((o) >> 3) & 0x70))

__device__ __forceinline__ void cp_async16(uint32_t saddr, const void* gptr) {
    asm volatile("cp.async.cg.shared.global [%0], [%1], 16;"
                 :: "r"(saddr), "l"(gptr));
}
__device__ __forceinline__ void ldmatrix_x4(uint32_t& r0, uint32_t& r1,
                                            uint32_t& r2, uint32_t& r3,
                                            uint32_t addr) {
    asm volatile("ldmatrix.sync.aligned.m8n8.x4.shared.b16 {%0,%1,%2,%3}, [%4];"
                 : "=r"(r0), "=r"(r1), "=r"(r2), "=r"(r3) : "r"(addr));
}
__device__ __forceinline__ void ldmatrix_x4_trans(uint32_t& r0, uint32_t& r1,
                                                  uint32_t& r2, uint32_t& r3,
                                                  uint32_t addr) {
    asm volatile("ldmatrix.sync.aligned.m8n8.x4.trans.shared.b16 {%0,%1,%2,%3}, [%4];"
                 : "=r"(r0), "=r"(r1), "=r"(r2), "=r"(r3) : "r"(addr));
}
__device__ __forceinline__ void mma_bf16(float* c,
                                         uint32_t a0, uint32_t a1, uint32_t a2, uint32_t a3,
                                         uint32_t b0, uint32_t b1) {
    asm volatile(
        "mma.sync.aligned.m16n8k16.row.col.f32.bf16.bf16.f32 "
        "{%0,%1,%2,%3}, {%4,%5,%6,%7}, {%8,%9}, {%0,%1,%2,%3};"
        : "+f"(c[0]), "+f"(c[1]), "+f"(c[2]), "+f"(c[3])
        : "r"(a0), "r"(a1), "r"(a2), "r"(a3), "r"(b0), "r"(b1));
}
__device__ __forceinline__ float ex2f(float x) {
    float r; asm("ex2.approx.f32 %0, %1;" : "=f"(r) : "f"(x)); return r;
}
__device__ __forceinline__ float sqrt_ap(float x) {
    float r; asm("sqrt.approx.f32 %0, %1;" : "=f"(r) : "f"(x)); return r;
}

// ---------------- epilogue helper -------------------------------------------
__device__ __forceinline__ void gemm_epilogue(
    int r0, int n0, int Nc, int ldc,
    const float* acc4, const float* __restrict__ bias,
    float* __restrict__ C, __nv_bfloat16* __restrict__ Cb,
    const float* __restrict__ res, const float* __restrict__ gamma, int mode)
{
    if (n0 >= Nc) return;
    float b0 = bias[n0], b1 = bias[n0 + 1];
    float v0 = acc4[0] + b0, v1 = acc4[1] + b1;
    float v2 = acc4[2] + b0, v3 = acc4[3] + b1;
    if (mode == 4) {
        int buf = n0 >> 9, cc = n0 & 511;
        __nv_bfloat16* dst = Cb + (size_t)buf * ((size_t)MTOT * DD)
                                + (size_t)r0 * DD + cc;
        *(__nv_bfloat162*)dst = __floats2bfloat162_rn(v0, v1);
        *(__nv_bfloat162*)(dst + 8 * DD) = __floats2bfloat162_rn(v2, v3);
    } else if (mode == 3) {
        int j = n0 >> 1;
        float s0 = v0 / (1.0f + __expf(-v0));
        float s2 = v2 / (1.0f + __expf(-v2));
        Cb[(size_t)r0 * ldc + j]       = __float2bfloat16(s0 * v1);
        Cb[(size_t)(r0 + 8) * ldc + j] = __float2bfloat16(s2 * v3);
    } else {
        float g0 = gamma[n0], g1 = gamma[n0 + 1];
        v0 = res[(size_t)r0 * ldc + n0]           + g0 * v0;
        v1 = res[(size_t)r0 * ldc + n0 + 1]       + g1 * v1;
        v2 = res[(size_t)(r0 + 8) * ldc + n0]     + g0 * v2;
        v3 = res[(size_t)(r0 + 8) * ldc + n0 + 1] + g1 * v3;
        *(float2*)&C[(size_t)r0 * ldc + n0]       = make_float2(v0, v1);
        *(float2*)&C[(size_t)(r0 + 8) * ldc + n0] = make_float2(v2, v3);
    }
}

// ---------------- GEMM mainloop body (templated on stage count) -------------
// C[M,N] = A[M,K] * Bw[N,K]^T + epilogue    CTA 128x64, BK=64, 8 warps.
template<int NSTAGE>
__device__ __forceinline__ void gemm_body(
    const __nv_bfloat16* __restrict__ A,
    const __nv_bfloat16* __restrict__ Bw,
    const float* __restrict__ bias,
    float* __restrict__ C, __nv_bfloat16* __restrict__ Cb,
    int ldc, int Nc, int K,
    const float* __restrict__ res, const float* __restrict__ gamma, int mode,
    char* smem)
{
    uint32_t sbase = smem_to_u32(smem);
    const int tid = threadIdx.x, lane = tid & 31, wid = tid >> 5;
    const int wm = wid & 1, wn = wid >> 1;
    const int bm = blockIdx.y * 128, bn = blockIdx.x * 64;

    const uint32_t STAGE = 24576u;
    const uint32_t BOFF  = 16384u;

    float acc[4][2][4];
    #pragma unroll
    for (int i = 0; i < 4; i++)
        #pragma unroll
        for (int j = 0; j < 2; j++)
            #pragma unroll
            for (int t = 0; t < 4; t++) acc[i][j][t] = 0.0f;

    const int lrow = tid >> 3;
    const int lcol = tid & 7;
    const int nch  = K >> 6;

    const int arow  = wm * 64 + (lane & 15);
    const int akoff = lane >> 4;
    const int brow  = wn * 16 + (lane & 7) + ((lane >> 4) << 3);
    const int bkoff = (lane >> 3) & 1;

    auto issue = [&](int c, int s) {
        uint32_t sb = sbase + (uint32_t)s * STAGE;
        #pragma unroll
        for (int i = 0; i < 4; i++) {
            int r = lrow + i * 32;
            uint32_t off = SMEM_SWIZZLE_128B((uint32_t)(r * 128 + lcol * 16));
            cp_async16(sb + off, A + (size_t)(bm + r) * K + c * 64 + lcol * 8);
        }
        #pragma unroll
        for (int i = 0; i < 2; i++) {
            int r = lrow + i * 32;
            uint32_t off = SMEM_SWIZZLE_128B((uint32_t)(r * 128 + lcol * 16));
            cp_async16(sb + BOFF + off, Bw + (size_t)(bn + r) * K + c * 64 + lcol * 8);
        }
        asm volatile("cp.async.commit_group;" ::: "memory");
    };

    issue(0, 0);
    if (NSTAGE == 3 && nch > 1) issue(1, 1);

    for (int c = 0; c < nch; c++) {
        int s = c % NSTAGE;
        if (NSTAGE == 2) {
            if (c + 1 < nch) {
                issue(c + 1, (c + 1) & 1);
                asm volatile("cp.async.wait_group 1;" ::: "memory");
            } else {
                asm volatile("cp.async.wait_group 0;" ::: "memory");
            }
        } else {
            if (c + 2 < nch) {
                issue(c + 2, (c + 2) % 3);
                asm volatile("cp.async.wait_group 2;" ::: "memory");
            } else if (c + 1 < nch) {
                asm volatile("cp.async.wait_group 1;" ::: "memory");
            } else {
                asm volatile("cp.async.wait_group 0;" ::: "memory");
            }
        }
        __syncthreads();

        uint32_t sa  = sbase + (uint32_t)s * STAGE;
        uint32_t sbb = sa + BOFF;
        #pragma unroll
        for (int ks = 0; ks < 4; ks++) {
            uint32_t a[4][4], b[4];
            #pragma unroll
            for (int mi = 0; mi < 4; mi++) {
                int r = arow + mi * 16;
                uint32_t addr = sa + SMEM_SWIZZLE_128B(
                    (uint32_t)(r * 128 + (2 * ks + akoff) * 16));
                ldmatrix_x4(a[mi][0], a[mi][1], a[mi][2], a[mi][3], addr);
            }
            {
                uint32_t addr = sbb + SMEM_SWIZZLE_128B(
                    (uint32_t)(brow * 128 + (2 * ks + bkoff) * 16));
                ldmatrix_x4(b[0], b[1], b[2], b[3], addr);
            }
            #pragma unroll
            for (int mi = 0; mi < 4; mi++) {
                mma_bf16(acc[mi][0], a[mi][0], a[mi][1], a[mi][2], a[mi][3], b[0], b[1]);
                mma_bf16(acc[mi][1], a[mi][0], a[mi][1], a[mi][2], a[mi][3], b[2], b[3]);
            }
        }
        __syncthreads();
    }

    int rbase = bm + wm * 64 + (lane >> 2);
    int cbase = bn + wn * 16 + 2 * (lane & 3);
    #pragma unroll
    for (int mi = 0; mi < 4; mi++)
        #pragma unroll
        for (int ni = 0; ni < 2; ni++)
            gemm_epilogue(rbase + mi * 16, cbase + ni * 8, Nc, ldc,
                          acc[mi][ni], bias, C, Cb, res, gamma, mode);
}

// 2-stage (48KB) — for residency-rich grids (qkv, fc1)
__global__ void __launch_bounds__(256) gemm_mma(
    const __nv_bfloat16* __restrict__ A, const __nv_bfloat16* __restrict__ Bw,
    const float* __restrict__ bias,
    float* __restrict__ C, __nv_bfloat16* __restrict__ Cb,
    int ldc, int Nc, int K,
    const float* __restrict__ res, const float* __restrict__ gamma, int mode)
{
    extern __shared__ char smem[];
    gemm_body<2>(A, Bw, bias, C, Cb, ldc, Nc, K, res, gamma, mode, smem);
}

// 3-stage (72KB) — for low-residency grids (o-proj, fc2: 256 CTAs)
__global__ void __launch_bounds__(256) gemm_mma3(
    const __nv_bfloat16* __restrict__ A, const __nv_bfloat16* __restrict__ Bw,
    const float* __restrict__ bias,
    float* __restrict__ C, __nv_bfloat16* __restrict__ Cb,
    int ldc, int Nc, int K,
    const float* __restrict__ res, const float* __restrict__ gamma, int mode)
{
    extern __shared__ char smem[];
    gemm_body<3>(A, Bw, bias, C, Cb, ldc, Nc, K, res, gamma, mode, smem);
}

// ---------------- LayerNorm -> bf16 (warp per row) --------------------------
__global__ void __launch_bounds__(128) ln_bf16_kernel(
    const float* __restrict__ x, const float* __restrict__ w,
    const float* __restrict__ b, __nv_bfloat16* __restrict__ out) {
    int warp = threadIdx.x >> 5, lane = threadIdx.x & 31;
    int row = blockIdx.x * 4 + warp;
    const float4* xr = (const float4*)(x + (size_t)row * DD);
    float4 v[4];
    float s = 0.0f, sq = 0.0f;
    #pragma unroll
    for (int i = 0; i < 4; i++) {
        v[i] = xr[lane + 32 * i];
        s  += v[i].x + v[i].y + v[i].z + v[i].w;
        sq += v[i].x*v[i].x + v[i].y*v[i].y + v[i].z*v[i].z + v[i].w*v[i].w;
    }
    #pragma unroll
    for (int o = 16; o; o >>= 1) {
        s  += __shfl_xor_sync(0xffffffffu, s,  o);
        sq += __shfl_xor_sync(0xffffffffu, sq, o);
    }
    float mean = s * (1.0f / DD);
    float var  = sq * (1.0f / DD) - mean * mean;
    float rstd = rsqrtf(var + 1e-5f);
    const float4* wr = (const float4*)w;
    const float4* br = (const float4*)b;
    uint2* orow = (uint2*)(out + (size_t)row * DD);
    #pragma unroll
    for (int i = 0; i < 4; i++) {
        float4 wv = wr[lane + 32 * i];
        float4 bv = br[lane + 32 * i];
        float o0 = (v[i].x - mean) * rstd * wv.x + bv.x;
        float o1 = (v[i].y - mean) * rstd * wv.y + bv.y;
        float o2 = (v[i].z - mean) * rstd * wv.z + bv.z;
        float o3 = (v[i].w - mean) * rstd * wv.w + bv.w;
        __nv_bfloat162 lo = __floats2bfloat162_rn(o0, o1);
        __nv_bfloat162 hi = __floats2bfloat162_rn(o2, o3);
        uint2 u; u.x = *(uint32_t*)&lo; u.y = *(uint32_t*)&hi;
        orow[lane + 32 * i] = u;
    }
}

// ---------------- merged weight convert (single launch) ---------------------
__global__ void conv_all_kernel(
    const float* __restrict__ qw, const float* __restrict__ kw,
    const float* __restrict__ vw, const float* __restrict__ ow,
    const float* __restrict__ qb, const float* __restrict__ kb,
    const float* __restrict__ vb2,
    const float* __restrict__ fc1_w, const float* __restrict__ fc1_b,
    const float* __restrict__ fc2_w,
    __nv_bfloat16* __restrict__ wqkv, __nv_bfloat16* __restrict__ wo,
    float* __restrict__ qkvb,
    __nv_bfloat16* __restrict__ fc1w, float* __restrict__ fc1b,
    __nv_bfloat16* __restrict__ fc2w)
{
    int idx = blockIdx.x * 256 + threadIdx.x;
    // fc2: [0, DD*HID2P)
    if (idx < DD * HID2P) {
        int n = idx / HID2P;
        int k = idx - n * HID2P;
        float v = (k < HID2) ? fc2_w[(size_t)n * HID2 + k] : 0.0f;
        fc2w[idx] = __float2bfloat16(v);
    }
    // fc1 interleave, vectorized: [0, HIDNP*DD/4)
    if (idx < HIDNP * (DD / 4)) {
        int r  = idx / (DD / 4);
        int c4 = idx - r * (DD / 4);
        int j = r >> 1, half = r & 1;
        float4 v = make_float4(0.f, 0.f, 0.f, 0.f);
        if (j < HID2)
            v = *(const float4*)&fc1_w[(size_t)(j + half * HID2) * DD + c4 * 4];
        __nv_bfloat162 lo = __floats2bfloat162_rn(v.x, v.y);
        __nv_bfloat162 hi = __floats2bfloat162_rn(v.z, v.w);
        uint2 u; u.x = *(uint32_t*)&lo; u.y = *(uint32_t*)&hi;
        *(uint2*)&fc1w[(size_t)r * DD + c4 * 4] = u;
    }
    // qkv + o weights: [0, DD*DD)
    if (idx < DD * DD) {
        wqkv[idx]               = __float2bfloat16(qw[idx]);
        wqkv[idx +     DD * DD] = __float2bfloat16(kw[idx]);
        wqkv[idx + 2 * DD * DD] = __float2bfloat16(vw[idx]);
        wo[idx]                 = __float2bfloat16(ow[idx]);
    }
    if (idx < QKVN) {
        float bv = (idx < 512) ? qb[idx] : (idx < 1024) ? kb[idx - 512] : vb2[idx - 1024];
        qkvb[idx] = bv;
    }
    if (idx < HIDNP) {
        int j = idx >> 1, half = idx & 1;
        fc1b[idx] = (j < HID2) ? fc1_b[j + half * HID2] : 0.0f;
    }
}

// ---------------- FA2 warp-MMA attention (128 queries/CTA, 8 warps) ---------
__global__ void __launch_bounds__(256) attn_mma(
    const __nv_bfloat16* __restrict__ q, const __nv_bfloat16* __restrict__ k,
    const __nv_bfloat16* __restrict__ vb, const float* __restrict__ coords,
    __nv_bfloat16* __restrict__ ctx)
{
    const int b = blockIdx.z, h = blockIdx.y, qt = blockIdx.x;
    const int tid = threadIdx.x, lane = tid & 31, wid = tid >> 5;

    __shared__ __align__(128) __nv_bfloat16 Ksm[2][64 * 64];
    __shared__ __align__(128) __nv_bfloat16 Vsm[2][64 * 64];
    __shared__ __align__(16) float2 Kc[2][64];

    const float LOG2E = 1.4426950408889634f;
    const float qscale = 0.125f * LOG2E;
    const float slope2 = exp2f(-(float)(h + 1)) * LOG2E;

    const int r0 = lane >> 2;
    const int gq0 = b * NTOK + qt * 128 + wid * 16 + r0;
    const int c0base = 2 * (lane & 3);

    uint32_t a[4][4];
    {
        const __nv_bfloat16* qp0 = q + (size_t)gq0 * DD + h * DHH;
        const __nv_bfloat16* qp1 = qp0 + 8 * DD;
        #pragma unroll
        for (int kt = 0; kt < 4; kt++) {
            a[kt][0] = *(const uint32_t*)(qp0 + kt * 16 + c0base);
            a[kt][1] = *(const uint32_t*)(qp1 + kt * 16 + c0base);
            a[kt][2] = *(const uint32_t*)(qp0 + kt * 16 + c0base + 8);
            a[kt][3] = *(const uint32_t*)(qp1 + kt * 16 + c0base + 8);
        }
    }
    float qx0 = coords[(size_t)gq0 * 2],       qy0 = coords[(size_t)gq0 * 2 + 1];
    float qx1 = coords[(size_t)(gq0 + 8) * 2], qy1 = coords[(size_t)(gq0 + 8) * 2 + 1];

    float o[8][4];
    #pragma unroll
    for (int j = 0; j < 8; j++)
        #pragma unroll
        for (int t = 0; t < 4; t++) o[j][t] = 0.0f;
    float m0 = -1e30f, m1 = -1e30f, l0 = 0.0f, l1 = 0.0f;

    uint32_t ksm_u = smem_to_u32(Ksm);
    uint32_t vsm_u = smem_to_u32(Vsm);
    uint32_t kc_u  = smem_to_u32(Kc);

    const int lr = tid >> 2, lq = tid & 3;
    const int brow = (lane & 7) + ((lane >> 4) << 3);
    const int bkoff = (lane >> 3) & 1;

    auto issue = [&](int kb, int s) {
        const __nv_bfloat16* kg = k  + (size_t)(b * NTOK + kb + lr) * DD + h * DHH + lq * 16;
        const __nv_bfloat16* vg = vb + (size_t)(b * NTOK + kb + lr) * DD + h * DHH + lq * 16;
        uint32_t o0 = SMEM_SWIZZLE_128B((uint32_t)(lr * 128 + lq * 32));
        uint32_t o1 = SMEM_SWIZZLE_128B((uint32_t)(lr * 128 + lq * 32 + 16));
        cp_async16(ksm_u + (uint32_t)s * 8192u + o0, kg);
        cp_async16(ksm_u + (uint32_t)s * 8192u + o1, kg + 8);
        cp_async16(vsm_u + (uint32_t)s * 8192u + o0, vg);
        cp_async16(vsm_u + (uint32_t)s * 8192u + o1, vg + 8);
        if (tid < 32) {
            cp_async16(kc_u + (uint32_t)s * 512u + (uint32_t)tid * 16u,
                       coords + (size_t)(b * NTOK + kb) * 2 + tid * 4);
        }
        asm volatile("cp.async.commit_group;" ::: "memory");
    };

    issue(0, 0);
    const int ntiles = NTOK / 64;
    for (int c = 0; c < ntiles; c++) {
        int s = c & 1;
        if (c + 1 < ntiles) {
            issue((c + 1) * 64, s ^ 1);
            asm volatile("cp.async.wait_group 1;" ::: "memory");
        } else {
            asm volatile("cp.async.wait_group 0;" ::: "memory");
        }
        __syncthreads();

        float sacc[8][4];
        #pragma unroll
        for (int j = 0; j < 8; j++)
            #pragma unroll
            for (int t = 0; t < 4; t++) sacc[j][t] = 0.0f;
        uint32_t kbase = ksm_u + (uint32_t)s * 8192u;
        #pragma unroll
        for (int ks = 0; ks < 4; ks++) {
            #pragma unroll
            for (int jj = 0; jj < 4; jj++) {
                uint32_t addr = kbase + SMEM_SWIZZLE_128B(
                    (uint32_t)((jj * 16 + brow) * 128 + (2 * ks + bkoff) * 16));
                uint32_t b0, b1, b2, b3;
                ldmatrix_x4(b0, b1, b2, b3, addr);
                mma_bf16(sacc[2 * jj],     a[ks][0], a[ks][1], a[ks][2], a[ks][3], b0, b1);
                mma_bf16(sacc[2 * jj + 1], a[ks][0], a[ks][1], a[ks][2], a[ks][3], b2, b3);
            }
        }

        float tm0 = -1e30f, tm1 = -1e30f;
        #pragma unroll
        for (int j = 0; j < 8; j++) {
            int cc = 8 * j + c0base;
            float2 k0 = Kc[s][cc], k1 = Kc[s][cc + 1];
            float dxa = qx0 - k0.x, dya = qy0 - k0.y;
            float dxb = qx0 - k1.x, dyb = qy0 - k1.y;
            float dxc = qx1 - k0.x, dyc = qy1 - k0.y;
            float dxd = qx1 - k1.x, dyd = qy1 - k1.y;
            sacc[j][0] = fmaf(sacc[j][0], qscale, -slope2 * sqrt_ap(dxa * dxa + dya * dya));
            sacc[j][1] = fmaf(sacc[j][1], qscale, -slope2 * sqrt_ap(dxb * dxb + dyb * dyb));
            sacc[j][2] = fmaf(sacc[j][2], qscale, -slope2 * sqrt_ap(dxc * dxc + dyc * dyc));
            sacc[j][3] = fmaf(sacc[j][3], qscale, -slope2 * sqrt_ap(dxd * dxd + dyd * dyd));
            tm0 = fmaxf(tm0, fmaxf(sacc[j][0], sacc[j][1]));
            tm1 = fmaxf(tm1, fmaxf(sacc[j][2], sacc[j][3]));
        }
        #pragma unroll
        for (int off = 1; off <= 2; off <<= 1) {
            tm0 = fmaxf(tm0, __shfl_xor_sync(0xffffffffu, tm0, off));
            tm1 = fmaxf(tm1, __shfl_xor_sync(0xffffffffu, tm1, off));
        }

        float mn0 = fmaxf(m0, tm0), mn1 = fmaxf(m1, tm1);
        float cr0 = ex2f(m0 - mn0), cr1 = ex2f(m1 - mn1);
        m0 = mn0; m1 = mn1;
        l0 *= cr0; l1 *= cr1;
        #pragma unroll
        for (int j = 0; j < 8; j++) {
            o[j][0] *= cr0; o[j][1] *= cr0;
            o[j][2] *= cr1; o[j][3] *= cr1;
        }
        #pragma unroll
        for (int j = 0; j < 8; j++) {
            float p0 = ex2f(sacc[j][0] - m0);
            float p1 = ex2f(sacc[j][1] - m0);
            float p2 = ex2f(sacc[j][2] - m1);
            float p3 = ex2f(sacc[j][3] - m1);
            l0 += p0 + p1; l1 += p2 + p3;
            sacc[j][0] = p0; sacc[j][1] = p1; sacc[j][2] = p2; sacc[j][3] = p3;
        }

        uint32_t vbase = vsm_u + (uint32_t)s * 8192u;
        #pragma unroll
        for (int t = 0; t < 4; t++) {
            __nv_bfloat162 h0 = __floats2bfloat162_rn(sacc[2*t][0],   sacc[2*t][1]);
            __nv_bfloat162 h1 = __floats2bfloat162_rn(sacc[2*t][2],   sacc[2*t][3]);
            __nv_bfloat162 h2 = __floats2bfloat162_rn(sacc[2*t+1][0], sacc[2*t+1][1]);
            __nv_bfloat162 h3 = __floats2bfloat162_rn(sacc[2*t+1][2], sacc[2*t+1][3]);
            uint32_t pa0 = *(uint32_t*)&h0, pa1 = *(uint32_t*)&h1;
            uint32_t pa2 = *(uint32_t*)&h2, pa3 = *(uint32_t*)&h3;
            #pragma unroll
            for (int g = 0; g < 4; g++) {
                uint32_t addr = vbase + SMEM_SWIZZLE_128B(
                    (uint32_t)((16 * t + (lane & 15)) * 128 + (16 * g + 8 * (lane >> 4)) * 2));
                uint32_t b0, b1, b2, b3;
                ldmatrix_x4_trans(b0, b1, b2, b3, addr);
                mma_bf16(o[2 * g],     pa0, pa1, pa2, pa3, b0, b1);
                mma_bf16(o[2 * g + 1], pa0, pa1, pa2, pa3, b2, b3);
            }
        }
        __syncthreads();
    }

    #pragma unroll
    for (int off = 1; off <= 2; off <<= 1) {
        l0 += __shfl_xor_sync(0xffffffffu, l0, off);
        l1 += __shfl_xor_sync(0xffffffffu, l1, off);
    }
    float inv0 = 1.0f / l0, inv1 = 1.0f / l1;
    __nv_bfloat16* crow0 = ctx + (size_t)gq0 * DD + h * DHH;
    __nv_bfloat16* crow1 = crow0 + 8 * DD;
    #pragma unroll
    for (int j = 0; j < 8; j++) {
        int d = 8 * j + c0base;
        *(__nv_bfloat162*)(crow0 + d) = __floats2bfloat162_rn(o[j][0] * inv0, o[j][1] * inv0);
        *(__nv_bfloat162*)(crow1 + d) = __floats2bfloat162_rn(o[j][2] * inv1, o[j][3] * inv1);
    }
}

// ---------------- launcher --------------------------------------------------
extern "C" void kernel_launch(void* const* d_in, const int* in_sizes, int n_in,
                              void* d_out, int out_size) {
    (void)in_sizes; (void)n_in; (void)out_size;
    const float* x      = (const float*)d_in[0];
    const float* coords = (const float*)d_in[1];
    const float* q_w    = (const float*)d_in[2];
    const float* q_b    = (const float*)d_in[3];
    const float* k_w    = (const float*)d_in[4];
    const float* k_b    = (const float*)d_in[5];
    const float* v_w    = (const float*)d_in[6];
    const float* v_b    = (const float*)d_in[7];
    const float* o_w    = (const float*)d_in[8];
    const float* o_b    = (const float*)d_in[9];
    const float* gamma1 = (const float*)d_in[10];
    const float* ln1_w  = (const float*)d_in[11];
    const float* ln1_b  = (const float*)d_in[12];
    const float* fc1_w  = (const float*)d_in[13];
    const float* fc1_b  = (const float*)d_in[14];
    const float* fc2_w  = (const float*)d_in[15];
    const float* fc2_b  = (const float*)d_in[16];
    const float* gamma2 = (const float*)d_in[17];
    const float* ln2_w  = (const float*)d_in[18];
    const float* ln2_b  = (const float*)d_in[19];
    float* out = (float*)d_out;

    __nv_bfloat16 *xn, *xn2, *ctxb, *qkv, *wqkv, *wo, *fc1w, *fc2w, *hsb;
    float *x1, *qkvb, *fc1b;
    cudaGetSymbolAddress((void**)&xn,   g_xn_bf);
    cudaGetSymbolAddress((void**)&xn2,  g_xn2_bf);
    cudaGetSymbolAddress((void**)&ctxb, g_ctx_bf);
    cudaGetSymbolAddress((void**)&qkv,  g_qkv_bf);
    cudaGetSymbolAddress((void**)&wqkv, g_wqkv_bf);
    cudaGetSymbolAddress((void**)&wo,   g_wo_bf);
    cudaGetSymbolAddress((void**)&fc1w, g_fc1w_bf);
    cudaGetSymbolAddress((void**)&fc2w, g_fc2w_bf);
    cudaGetSymbolAddress((void**)&hsb,  g_hs_bf);
    cudaGetSymbolAddress((void**)&x1,   g_x1);
    cudaGetSymbolAddress((void**)&qkvb, g_qkvb);
    cudaGetSymbolAddress((void**)&fc1b, g_fc1b);

    const int SMEM_GEMM  = 49152;
    const int SMEM_GEMM3 = 73728;
    cudaFuncSetAttribute(gemm_mma3, cudaFuncAttributeMaxDynamicSharedMemorySize, SMEM_GEMM3);

    // merged weight conversions (single launch)
    {
        int total = DD * HID2P;   // largest range
        conv_all_kernel<<<(total + 255) / 256, 256>>>(
            q_w, k_w, v_w, o_w, q_b, k_b, v_b, fc1_w, fc1_b, fc2_w,
            wqkv, wo, qkvb, fc1w, fc1b, fc2w);
    }

    ln_bf16_kernel<<<MTOT / 4, 128>>>(x, ln1_w, ln1_b, xn);

    // fused QKV projection (2-stage; grid 24x32 = 768 CTAs)
    dim3 gqkv(QKVN / 64, MTOT / 128);
    gemm_mma<<<gqkv, 256, SMEM_GEMM>>>(xn, wqkv, qkvb, nullptr, qkv, DD, QKVN, DD,
                                       nullptr, nullptr, 4);

    // FA2 attention (128 queries/CTA)
    dim3 gattn(NTOK / 128, HH, BB);
    attn_mma<<<gattn, 256>>>(qkv, qkv + (size_t)MTOT * DD, qkv + 2 * (size_t)MTOT * DD,
                             coords, ctxb);

    // O projection + residual1 (3-stage; grid 8x32 = 256 CTAs, low residency)
    dim3 gproj(DD / 64, MTOT / 128);
    gemm_mma3<<<gproj, 256, SMEM_GEMM3>>>(ctxb, wo, o_b, x1, nullptr, DD, DD, DD, x, gamma1, 1);

    ln_bf16_kernel<<<MTOT / 4, 128>>>(x1, ln2_w, ln2_b, xn2);

    // fc1 + fused SwiGLU (2-stage; grid 44x32 = 1408 CTAs)
    dim3 gfc1(HIDNP / 64, MTOT / 128);
    gemm_mma<<<gfc1, 256, SMEM_GEMM>>>(xn2, fc1w, fc1b, nullptr, hsb, HID2P, HIDNP, DD,
                                       nullptr, nullptr, 3);

    // fc2 + residual2 -> out (3-stage)
    gemm_mma3<<<gproj, 256, SMEM_GEMM3>>>(hsb, fc2w, fc2_b, out, nullptr, DD, DD, HID2P,
                                          x1, gamma2, 1);
}

// round 14
// speedup vs baseline: 1.1447x; 1.0663x over previous
#include <cuda_runtime.h>
#include <cuda_bf16.h>
#include <cstdint>
#include <math.h>

#define BB 2
#define NTOK 2048
#define DD 512
#define HH 8
#define DHH 64
#define HIDN 2730
#define HID2 1365
#define HID2P 1408     // padded (interleaved/2) width of hs
#define HIDNP 2816     // padded interleaved N for fc1
#define MTOT (BB*NTOK) // 4096
#define QKVN 1536

// ---------------- scratch (static device globals) ---------------------------
__device__ __nv_bfloat16 g_xn_bf [MTOT*DD];
__device__ __nv_bfloat16 g_xn2_bf[MTOT*DD];
__device__ __nv_bfloat16 g_ctx_bf[MTOT*DD];
__device__ __nv_bfloat16 g_qkv_bf[3*MTOT*DD];
__device__ __nv_bfloat16 g_wqkv_bf[QKVN*DD];
__device__ float         g_qkvb  [QKVN];
__device__ __nv_bfloat16 g_wo_bf [DD*DD];
__device__ __nv_bfloat16 g_fc1w_bf[(size_t)HIDNP*DD];   // interleaved h1/h2 rows
__device__ float         g_fc1b  [HIDNP];               // interleaved bias
__device__ __nv_bfloat16 g_fc2w_bf[(size_t)DD*HID2P];
__device__ __nv_bfloat16 g_hs_bf  [(size_t)MTOT*HID2P];
__device__ float g_x1  [MTOT*DD];

// ---------------- base-ISA helpers ------------------------------------------
__device__ __forceinline__ uint32_t smem_to_u32(const void* p) {
    uint32_t a;
    asm("{ .reg .u64 t; cvta.to.shared.u64 t, %1; cvt.u32.u64 %0, t; }"
        : "=r"(a) : "l"(p));
    return a;
}
#define SMEM_SWIZZLE_128B(o) ((o) ^ (((o) >> 3) & 0x70))

__device__ __forceinline__ void cp_async16(uint32_t saddr, const void* gptr) {
    asm volatile("cp.async.cg.shared.global [%0], [%1], 16;"
                 :: "r"(saddr), "l"(gptr));
}
__device__ __forceinline__ void ldmatrix_x4(uint32_t& r0, uint32_t& r1,
                                            uint32_t& r2, uint32_t& r3,
                                            uint32_t addr) {
    asm volatile("ldmatrix.sync.aligned.m8n8.x4.shared.b16 {%0,%1,%2,%3}, [%4];"
                 : "=r"(r0), "=r"(r1), "=r"(r2), "=r"(r3) : "r"(addr));
}
__device__ __forceinline__ void ldmatrix_x4_trans(uint32_t& r0, uint32_t& r1,
                                                  uint32_t& r2, uint32_t& r3,
                                                  uint32_t addr) {
    asm volatile("ldmatrix.sync.aligned.m8n8.x4.trans.shared.b16 {%0,%1,%2,%3}, [%4];"
                 : "=r"(r0), "=r"(r1), "=r"(r2), "=r"(r3) : "r"(addr));
}
__device__ __forceinline__ void mma_bf16(float* c,
                                         uint32_t a0, uint32_t a1, uint32_t a2, uint32_t a3,
                                         uint32_t b0, uint32_t b1) {
    asm volatile(
        "mma.sync.aligned.m16n8k16.row.col.f32.bf16.bf16.f32 "
        "{%0,%1,%2,%3}, {%4,%5,%6,%7}, {%8,%9}, {%0,%1,%2,%3};"
        : "+f"(c[0]), "+f"(c[1]), "+f"(c[2]), "+f"(c[3])
        : "r"(a0), "r"(a1), "r"(a2), "r"(a3), "r"(b0), "r"(b1));
}
__device__ __forceinline__ float ex2f(float x) {
    float r; asm("ex2.approx.f32 %0, %1;" : "=f"(r) : "f"(x)); return r;
}
__device__ __forceinline__ float sqrt_ap(float x) {
    float r; asm("sqrt.approx.f32 %0, %1;" : "=f"(r) : "f"(x)); return r;
}

// ---------------- epilogue helper -------------------------------------------
__device__ __forceinline__ void gemm_epilogue(
    int r0, int n0, int Nc, int ldc,
    const float* acc4, const float* __restrict__ bias,
    float* __restrict__ C, __nv_bfloat16* __restrict__ Cb,
    const float* __restrict__ res, const float* __restrict__ gamma, int mode)
{
    if (n0 >= Nc) return;
    float b0 = bias[n0], b1 = bias[n0 + 1];
    float v0 = acc4[0] + b0, v1 = acc4[1] + b1;
    float v2 = acc4[2] + b0, v3 = acc4[3] + b1;
    if (mode == 4) {
        int buf = n0 >> 9, cc = n0 & 511;
        __nv_bfloat16* dst = Cb + (size_t)buf * ((size_t)MTOT * DD)
                                + (size_t)r0 * DD + cc;
        *(__nv_bfloat162*)dst = __floats2bfloat162_rn(v0, v1);
        *(__nv_bfloat162*)(dst + 8 * DD) = __floats2bfloat162_rn(v2, v3);
    } else if (mode == 3) {
        int j = n0 >> 1;
        float s0 = v0 / (1.0f + __expf(-v0));
        float s2 = v2 / (1.0f + __expf(-v2));
        Cb[(size_t)r0 * ldc + j]       = __float2bfloat16(s0 * v1);
        Cb[(size_t)(r0 + 8) * ldc + j] = __float2bfloat16(s2 * v3);
    } else {
        float g0 = gamma[n0], g1 = gamma[n0 + 1];
        v0 = res[(size_t)r0 * ldc + n0]           + g0 * v0;
        v1 = res[(size_t)r0 * ldc + n0 + 1]       + g1 * v1;
        v2 = res[(size_t)(r0 + 8) * ldc + n0]     + g0 * v2;
        v3 = res[(size_t)(r0 + 8) * ldc + n0 + 1] + g1 * v3;
        *(float2*)&C[(size_t)r0 * ldc + n0]       = make_float2(v0, v1);
        *(float2*)&C[(size_t)(r0 + 8) * ldc + n0] = make_float2(v2, v3);
    }
}

// ---------------- GEMM mainloop body (templated on stage count) -------------
template<int NSTAGE>
__device__ __forceinline__ void gemm_body(
    const __nv_bfloat16* __restrict__ A,
    const __nv_bfloat16* __restrict__ Bw,
    const float* __restrict__ bias,
    float* __restrict__ C, __nv_bfloat16* __restrict__ Cb,
    int ldc, int Nc, int K,
    const float* __restrict__ res, const float* __restrict__ gamma, int mode,
    char* smem)
{
    uint32_t sbase = smem_to_u32(smem);
    const int tid = threadIdx.x, lane = tid & 31, wid = tid >> 5;
    const int wm = wid & 1, wn = wid >> 1;
    const int bm = blockIdx.y * 128, bn = blockIdx.x * 64;

    const uint32_t STAGE = 24576u;
    const uint32_t BOFF  = 16384u;

    float acc[4][2][4];
    #pragma unroll
    for (int i = 0; i < 4; i++)
        #pragma unroll
        for (int j = 0; j < 2; j++)
            #pragma unroll
            for (int t = 0; t < 4; t++) acc[i][j][t] = 0.0f;

    const int lrow = tid >> 3;
    const int lcol = tid & 7;
    const int nch  = K >> 6;

    const int arow  = wm * 64 + (lane & 15);
    const int akoff = lane >> 4;
    const int brow  = wn * 16 + (lane & 7) + ((lane >> 4) << 3);
    const int bkoff = (lane >> 3) & 1;

    auto issue = [&](int c, int s) {
        uint32_t sb = sbase + (uint32_t)s * STAGE;
        #pragma unroll
        for (int i = 0; i < 4; i++) {
            int r = lrow + i * 32;
            uint32_t off = SMEM_SWIZZLE_128B((uint32_t)(r * 128 + lcol * 16));
            cp_async16(sb + off, A + (size_t)(bm + r) * K + c * 64 + lcol * 8);
        }
        #pragma unroll
        for (int i = 0; i < 2; i++) {
            int r = lrow + i * 32;
            uint32_t off = SMEM_SWIZZLE_128B((uint32_t)(r * 128 + lcol * 16));
            cp_async16(sb + BOFF + off, Bw + (size_t)(bn + r) * K + c * 64 + lcol * 8);
        }
        asm volatile("cp.async.commit_group;" ::: "memory");
    };

    issue(0, 0);
    if (NSTAGE == 3 && nch > 1) issue(1, 1);

    for (int c = 0; c < nch; c++) {
        int s = c % NSTAGE;
        if (NSTAGE == 2) {
            if (c + 1 < nch) {
                issue(c + 1, (c + 1) & 1);
                asm volatile("cp.async.wait_group 1;" ::: "memory");
            } else {
                asm volatile("cp.async.wait_group 0;" ::: "memory");
            }
        } else {
            if (c + 2 < nch) {
                issue(c + 2, (c + 2) % 3);
                asm volatile("cp.async.wait_group 2;" ::: "memory");
            } else if (c + 1 < nch) {
                asm volatile("cp.async.wait_group 1;" ::: "memory");
            } else {
                asm volatile("cp.async.wait_group 0;" ::: "memory");
            }
        }
        __syncthreads();

        uint32_t sa  = sbase + (uint32_t)s * STAGE;
        uint32_t sbb = sa + BOFF;
        #pragma unroll
        for (int ks = 0; ks < 4; ks++) {
            uint32_t a[4][4], b[4];
            #pragma unroll
            for (int mi = 0; mi < 4; mi++) {
                int r = arow + mi * 16;
                uint32_t addr = sa + SMEM_SWIZZLE_128B(
                    (uint32_t)(r * 128 + (2 * ks + akoff) * 16));
                ldmatrix_x4(a[mi][0], a[mi][1], a[mi][2], a[mi][3], addr);
            }
            {
                uint32_t addr = sbb + SMEM_SWIZZLE_128B(
                    (uint32_t)(brow * 128 + (2 * ks + bkoff) * 16));
                ldmatrix_x4(b[0], b[1], b[2], b[3], addr);
            }
            #pragma unroll
            for (int mi = 0; mi < 4; mi++) {
                mma_bf16(acc[mi][0], a[mi][0], a[mi][1], a[mi][2], a[mi][3], b[0], b[1]);
                mma_bf16(acc[mi][1], a[mi][0], a[mi][1], a[mi][2], a[mi][3], b[2], b[3]);
            }
        }
        __syncthreads();
    }

    int rbase = bm + wm * 64 + (lane >> 2);
    int cbase = bn + wn * 16 + 2 * (lane & 3);
    #pragma unroll
    for (int mi = 0; mi < 4; mi++)
        #pragma unroll
        for (int ni = 0; ni < 2; ni++)
            gemm_epilogue(rbase + mi * 16, cbase + ni * 8, Nc, ldc,
                          acc[mi][ni], bias, C, Cb, res, gamma, mode);
}

// 2-stage (48KB) — for residency-rich grids (qkv, fc1)
__global__ void __launch_bounds__(256) gemm_mma(
    const __nv_bfloat16* __restrict__ A, const __nv_bfloat16* __restrict__ Bw,
    const float* __restrict__ bias,
    float* __restrict__ C, __nv_bfloat16* __restrict__ Cb,
    int ldc, int Nc, int K,
    const float* __restrict__ res, const float* __restrict__ gamma, int mode)
{
    extern __shared__ char smem[];
    gemm_body<2>(A, Bw, bias, C, Cb, ldc, Nc, K, res, gamma, mode, smem);
}

// 3-stage (72KB) — for low-residency grids (o-proj, fc2: 256 CTAs)
__global__ void __launch_bounds__(256) gemm_mma3(
    const __nv_bfloat16* __restrict__ A, const __nv_bfloat16* __restrict__ Bw,
    const float* __restrict__ bias,
    float* __restrict__ C, __nv_bfloat16* __restrict__ Cb,
    int ldc, int Nc, int K,
    const float* __restrict__ res, const float* __restrict__ gamma, int mode)
{
    extern __shared__ char smem[];
    gemm_body<3>(A, Bw, bias, C, Cb, ldc, Nc, K, res, gamma, mode, smem);
}

// ---------------- LayerNorm -> bf16 (warp per row) --------------------------
__global__ void __launch_bounds__(128) ln_bf16_kernel(
    const float* __restrict__ x, const float* __restrict__ w,
    const float* __restrict__ b, __nv_bfloat16* __restrict__ out) {
    int warp = threadIdx.x >> 5, lane = threadIdx.x & 31;
    int row = blockIdx.x * 4 + warp;
    const float4* xr = (const float4*)(x + (size_t)row * DD);
    float4 v[4];
    float s = 0.0f, sq = 0.0f;
    #pragma unroll
    for (int i = 0; i < 4; i++) {
        v[i] = xr[lane + 32 * i];
        s  += v[i].x + v[i].y + v[i].z + v[i].w;
        sq += v[i].x*v[i].x + v[i].y*v[i].y + v[i].z*v[i].z + v[i].w*v[i].w;
    }
    #pragma unroll
    for (int o = 16; o; o >>= 1) {
        s  += __shfl_xor_sync(0xffffffffu, s,  o);
        sq += __shfl_xor_sync(0xffffffffu, sq, o);
    }
    float mean = s * (1.0f / DD);
    float var  = sq * (1.0f / DD) - mean * mean;
    float rstd = rsqrtf(var + 1e-5f);
    const float4* wr = (const float4*)w;
    const float4* br = (const float4*)b;
    uint2* orow = (uint2*)(out + (size_t)row * DD);
    #pragma unroll
    for (int i = 0; i < 4; i++) {
        float4 wv = wr[lane + 32 * i];
        float4 bv = br[lane + 32 * i];
        float o0 = (v[i].x - mean) * rstd * wv.x + bv.x;
        float o1 = (v[i].y - mean) * rstd * wv.y + bv.y;
        float o2 = (v[i].z - mean) * rstd * wv.z + bv.z;
        float o3 = (v[i].w - mean) * rstd * wv.w + bv.w;
        __nv_bfloat162 lo = __floats2bfloat162_rn(o0, o1);
        __nv_bfloat162 hi = __floats2bfloat162_rn(o2, o3);
        uint2 u; u.x = *(uint32_t*)&lo; u.y = *(uint32_t*)&hi;
        orow[lane + 32 * i] = u;
    }
}

// ---------------- merged weight convert (single launch) ---------------------
__global__ void conv_all_kernel(
    const float* __restrict__ qw, const float* __restrict__ kw,
    const float* __restrict__ vw, const float* __restrict__ ow,
    const float* __restrict__ qb, const float* __restrict__ kb,
    const float* __restrict__ vb2,
    const float* __restrict__ fc1_w, const float* __restrict__ fc1_b,
    const float* __restrict__ fc2_w,
    __nv_bfloat16* __restrict__ wqkv, __nv_bfloat16* __restrict__ wo,
    float* __restrict__ qkvb,
    __nv_bfloat16* __restrict__ fc1w, float* __restrict__ fc1b,
    __nv_bfloat16* __restrict__ fc2w)
{
    int idx = blockIdx.x * 256 + threadIdx.x;
    if (idx < DD * HID2P) {
        int n = idx / HID2P;
        int k = idx - n * HID2P;
        float v = (k < HID2) ? fc2_w[(size_t)n * HID2 + k] : 0.0f;
        fc2w[idx] = __float2bfloat16(v);
    }
    if (idx < HIDNP * (DD / 4)) {
        int r  = idx / (DD / 4);
        int c4 = idx - r * (DD / 4);
        int j = r >> 1, half = r & 1;
        float4 v = make_float4(0.f, 0.f, 0.f, 0.f);
        if (j < HID2)
            v = *(const float4*)&fc1_w[(size_t)(j + half * HID2) * DD + c4 * 4];
        __nv_bfloat162 lo = __floats2bfloat162_rn(v.x, v.y);
        __nv_bfloat162 hi = __floats2bfloat162_rn(v.z, v.w);
        uint2 u; u.x = *(uint32_t*)&lo; u.y = *(uint32_t*)&hi;
        *(uint2*)&fc1w[(size_t)r * DD + c4 * 4] = u;
    }
    if (idx < DD * DD) {
        wqkv[idx]               = __float2bfloat16(qw[idx]);
        wqkv[idx +     DD * DD] = __float2bfloat16(kw[idx]);
        wqkv[idx + 2 * DD * DD] = __float2bfloat16(vw[idx]);
        wo[idx]                 = __float2bfloat16(ow[idx]);
    }
    if (idx < QKVN) {
        float bv = (idx < 512) ? qb[idx] : (idx < 1024) ? kb[idx - 512] : vb2[idx - 1024];
        qkvb[idx] = bv;
    }
    if (idx < HIDNP) {
        int j = idx >> 1, half = idx & 1;
        fc1b[idx] = (j < HID2) ? fc1_b[j + half * HID2] : 0.0f;
    }
}

// ---------------- FA2 warp-MMA attention (128 queries/CTA, 8 warps) ---------
// __launch_bounds__(256, 2): cap regs at 128 so 2 CTAs co-reside per SM,
// letting one CTA's softmax ALU/MUFU overlap the other's MMA phase.
__global__ void __launch_bounds__(256, 2) attn_mma(
    const __nv_bfloat16* __restrict__ q, const __nv_bfloat16* __restrict__ k,
    const __nv_bfloat16* __restrict__ vb, const float* __restrict__ coords,
    __nv_bfloat16* __restrict__ ctx)
{
    const int b = blockIdx.z, h = blockIdx.y, qt = blockIdx.x;
    const int tid = threadIdx.x, lane = tid & 31, wid = tid >> 5;

    __shared__ __align__(128) __nv_bfloat16 Ksm[2][64 * 64];
    __shared__ __align__(128) __nv_bfloat16 Vsm[2][64 * 64];
    __shared__ __align__(16) float2 Kc[2][64];

    const float LOG2E = 1.4426950408889634f;
    const float qscale = 0.125f * LOG2E;
    const float slope2 = exp2f(-(float)(h + 1)) * LOG2E;

    const int r0 = lane >> 2;
    const int gq0 = b * NTOK + qt * 128 + wid * 16 + r0;
    const int c0base = 2 * (lane & 3);

    uint32_t a[4][4];
    {
        const __nv_bfloat16* qp0 = q + (size_t)gq0 * DD + h * DHH;
        const __nv_bfloat16* qp1 = qp0 + 8 * DD;
        #pragma unroll
        for (int kt = 0; kt < 4; kt++) {
            a[kt][0] = *(const uint32_t*)(qp0 + kt * 16 + c0base);
            a[kt][1] = *(const uint32_t*)(qp1 + kt * 16 + c0base);
            a[kt][2] = *(const uint32_t*)(qp0 + kt * 16 + c0base + 8);
            a[kt][3] = *(const uint32_t*)(qp1 + kt * 16 + c0base + 8);
        }
    }
    float qx0 = coords[(size_t)gq0 * 2],       qy0 = coords[(size_t)gq0 * 2 + 1];
    float qx1 = coords[(size_t)(gq0 + 8) * 2], qy1 = coords[(size_t)(gq0 + 8) * 2 + 1];

    float o[8][4];
    #pragma unroll
    for (int j = 0; j < 8; j++)
        #pragma unroll
        for (int t = 0; t < 4; t++) o[j][t] = 0.0f;
    float m0 = -1e30f, m1 = -1e30f, l0 = 0.0f, l1 = 0.0f;

    uint32_t ksm_u = smem_to_u32(Ksm);
    uint32_t vsm_u = smem_to_u32(Vsm);
    uint32_t kc_u  = smem_to_u32(Kc);

    const int lr = tid >> 2, lq = tid & 3;
    const int brow = (lane & 7) + ((lane >> 4) << 3);
    const int bkoff = (lane >> 3) & 1;

    auto issue = [&](int kb, int s) {
        const __nv_bfloat16* kg = k  + (size_t)(b * NTOK + kb + lr) * DD + h * DHH + lq * 16;
        const __nv_bfloat16* vg = vb + (size_t)(b * NTOK + kb + lr) * DD + h * DHH + lq * 16;
        uint32_t o0 = SMEM_SWIZZLE_128B((uint32_t)(lr * 128 + lq * 32));
        uint32_t o1 = SMEM_SWIZZLE_128B((uint32_t)(lr * 128 + lq * 32 + 16));
        cp_async16(ksm_u + (uint32_t)s * 8192u + o0, kg);
        cp_async16(ksm_u + (uint32_t)s * 8192u + o1, kg + 8);
        cp_async16(vsm_u + (uint32_t)s * 8192u + o0, vg);
        cp_async16(vsm_u + (uint32_t)s * 8192u + o1, vg + 8);
        if (tid < 32) {
            cp_async16(kc_u + (uint32_t)s * 512u + (uint32_t)tid * 16u,
                       coords + (size_t)(b * NTOK + kb) * 2 + tid * 4);
        }
        asm volatile("cp.async.commit_group;" ::: "memory");
    };

    issue(0, 0);
    const int ntiles = NTOK / 64;
    for (int c = 0; c < ntiles; c++) {
        int s = c & 1;
        if (c + 1 < ntiles) {
            issue((c + 1) * 64, s ^ 1);
            asm volatile("cp.async.wait_group 1;" ::: "memory");
        } else {
            asm volatile("cp.async.wait_group 0;" ::: "memory");
        }
        __syncthreads();

        float sacc[8][4];
        #pragma unroll
        for (int j = 0; j < 8; j++)
            #pragma unroll
            for (int t = 0; t < 4; t++) sacc[j][t] = 0.0f;
        uint32_t kbase = ksm_u + (uint32_t)s * 8192u;
        #pragma unroll
        for (int ks = 0; ks < 4; ks++) {
            #pragma unroll
            for (int jj = 0; jj < 4; jj++) {
                uint32_t addr = kbase + SMEM_SWIZZLE_128B(
                    (uint32_t)((jj * 16 + brow) * 128 + (2 * ks + bkoff) * 16));
                uint32_t b0, b1, b2, b3;
                ldmatrix_x4(b0, b1, b2, b3, addr);
                mma_bf16(sacc[2 * jj],     a[ks][0], a[ks][1], a[ks][2], a[ks][3], b0, b1);
                mma_bf16(sacc[2 * jj + 1], a[ks][0], a[ks][1], a[ks][2], a[ks][3], b2, b3);
            }
        }

        float tm0 = -1e30f, tm1 = -1e30f;
        #pragma unroll
        for (int j = 0; j < 8; j++) {
            int cc = 8 * j + c0base;
            float2 k0 = Kc[s][cc], k1 = Kc[s][cc + 1];
            float dxa = qx0 - k0.x, dya = qy0 - k0.y;
            float dxb = qx0 - k1.x, dyb = qy0 - k1.y;
            float dxc = qx1 - k0.x, dyc = qy1 - k0.y;
            float dxd = qx1 - k1.x, dyd = qy1 - k1.y;
            sacc[j][0] = fmaf(sacc[j][0], qscale, -slope2 * sqrt_ap(dxa * dxa + dya * dya));
            sacc[j][1] = fmaf(sacc[j][1], qscale, -slope2 * sqrt_ap(dxb * dxb + dyb * dyb));
            sacc[j][2] = fmaf(sacc[j][2], qscale, -slope2 * sqrt_ap(dxc * dxc + dyc * dyc));
            sacc[j][3] = fmaf(sacc[j][3], qscale, -slope2 * sqrt_ap(dxd * dxd + dyd * dyd));
            tm0 = fmaxf(tm0, fmaxf(sacc[j][0], sacc[j][1]));
            tm1 = fmaxf(tm1, fmaxf(sacc[j][2], sacc[j][3]));
        }
        #pragma unroll
        for (int off = 1; off <= 2; off <<= 1) {
            tm0 = fmaxf(tm0, __shfl_xor_sync(0xffffffffu, tm0, off));
            tm1 = fmaxf(tm1, __shfl_xor_sync(0xffffffffu, tm1, off));
        }

        float mn0 = fmaxf(m0, tm0), mn1 = fmaxf(m1, tm1);
        float cr0 = ex2f(m0 - mn0), cr1 = ex2f(m1 - mn1);
        m0 = mn0; m1 = mn1;
        l0 *= cr0; l1 *= cr1;
        #pragma unroll
        for (int j = 0; j < 8; j++) {
            o[j][0] *= cr0; o[j][1] *= cr0;
            o[j][2] *= cr1; o[j][3] *= cr1;
        }
        #pragma unroll
        for (int j = 0; j < 8; j++) {
            float p0 = ex2f(sacc[j][0] - m0);
            float p1 = ex2f(sacc[j][1] - m0);
            float p2 = ex2f(sacc[j][2] - m1);
            float p3 = ex2f(sacc[j][3] - m1);
            l0 += p0 + p1; l1 += p2 + p3;
            sacc[j][0] = p0; sacc[j][1] = p1; sacc[j][2] = p2; sacc[j][3] = p3;
        }

        uint32_t vbase = vsm_u + (uint32_t)s * 8192u;
        #pragma unroll
        for (int t = 0; t < 4; t++) {
            __nv_bfloat162 h0 = __floats2bfloat162_rn(sacc[2*t][0],   sacc[2*t][1]);
            __nv_bfloat162 h1 = __floats2bfloat162_rn(sacc[2*t][2],   sacc[2*t][3]);
            __nv_bfloat162 h2 = __floats2bfloat162_rn(sacc[2*t+1][0], sacc[2*t+1][1]);
            __nv_bfloat162 h3 = __floats2bfloat162_rn(sacc[2*t+1][2], sacc[2*t+1][3]);
            uint32_t pa0 = *(uint32_t*)&h0, pa1 = *(uint32_t*)&h1;
            uint32_t pa2 = *(uint32_t*)&h2, pa3 = *(uint32_t*)&h3;
            #pragma unroll
            for (int g = 0; g < 4; g++) {
                uint32_t addr = vbase + SMEM_SWIZZLE_128B(
                    (uint32_t)((16 * t + (lane & 15)) * 128 + (16 * g + 8 * (lane >> 4)) * 2));
                uint32_t b0, b1, b2, b3;
                ldmatrix_x4_trans(b0, b1, b2, b3, addr);
                mma_bf16(o[2 * g],     pa0, pa1, pa2, pa3, b0, b1);
                mma_bf16(o[2 * g + 1], pa0, pa1, pa2, pa3, b2, b3);
            }
        }
        __syncthreads();
    }

    #pragma unroll
    for (int off = 1; off <= 2; off <<= 1) {
        l0 += __shfl_xor_sync(0xffffffffu, l0, off);
        l1 += __shfl_xor_sync(0xffffffffu, l1, off);
    }
    float inv0 = 1.0f / l0, inv1 = 1.0f / l1;
    __nv_bfloat16* crow0 = ctx + (size_t)gq0 * DD + h * DHH;
    __nv_bfloat16* crow1 = crow0 + 8 * DD;
    #pragma unroll
    for (int j = 0; j < 8; j++) {
        int d = 8 * j + c0base;
        *(__nv_bfloat162*)(crow0 + d) = __floats2bfloat162_rn(o[j][0] * inv0, o[j][1] * inv0);
        *(__nv_bfloat162*)(crow1 + d) = __floats2bfloat162_rn(o[j][2] * inv1, o[j][3] * inv1);
    }
}

// ---------------- launcher --------------------------------------------------
extern "C" void kernel_launch(void* const* d_in, const int* in_sizes, int n_in,
                              void* d_out, int out_size) {
    (void)in_sizes; (void)n_in; (void)out_size;
    const float* x      = (const float*)d_in[0];
    const float* coords = (const float*)d_in[1];
    const float* q_w    = (const float*)d_in[2];
    const float* q_b    = (const float*)d_in[3];
    const float* k_w    = (const float*)d_in[4];
    const float* k_b    = (const float*)d_in[5];
    const float* v_w    = (const float*)d_in[6];
    const float* v_b    = (const float*)d_in[7];
    const float* o_w    = (const float*)d_in[8];
    const float* o_b    = (const float*)d_in[9];
    const float* gamma1 = (const float*)d_in[10];
    const float* ln1_w  = (const float*)d_in[11];
    const float* ln1_b  = (const float*)d_in[12];
    const float* fc1_w  = (const float*)d_in[13];
    const float* fc1_b  = (const float*)d_in[14];
    const float* fc2_w  = (const float*)d_in[15];
    const float* fc2_b  = (const float*)d_in[16];
    const float* gamma2 = (const float*)d_in[17];
    const float* ln2_w  = (const float*)d_in[18];
    const float* ln2_b  = (const float*)d_in[19];
    float* out = (float*)d_out;

    __nv_bfloat16 *xn, *xn2, *ctxb, *qkv, *wqkv, *wo, *fc1w, *fc2w, *hsb;
    float *x1, *qkvb, *fc1b;
    cudaGetSymbolAddress((void**)&xn,   g_xn_bf);
    cudaGetSymbolAddress((void**)&xn2,  g_xn2_bf);
    cudaGetSymbolAddress((void**)&ctxb, g_ctx_bf);
    cudaGetSymbolAddress((void**)&qkv,  g_qkv_bf);
    cudaGetSymbolAddress((void**)&wqkv, g_wqkv_bf);
    cudaGetSymbolAddress((void**)&wo,   g_wo_bf);
    cudaGetSymbolAddress((void**)&fc1w, g_fc1w_bf);
    cudaGetSymbolAddress((void**)&fc2w, g_fc2w_bf);
    cudaGetSymbolAddress((void**)&hsb,  g_hs_bf);
    cudaGetSymbolAddress((void**)&x1,   g_x1);
    cudaGetSymbolAddress((void**)&qkvb, g_qkvb);
    cudaGetSymbolAddress((void**)&fc1b, g_fc1b);

    const int SMEM_GEMM  = 49152;
    const int SMEM_GEMM3 = 73728;
    cudaFuncSetAttribute(gemm_mma3, cudaFuncAttributeMaxDynamicSharedMemorySize, SMEM_GEMM3);

    // merged weight conversions (single launch)
    {
        int total = DD * HID2P;
        conv_all_kernel<<<(total + 255) / 256, 256>>>(
            q_w, k_w, v_w, o_w, q_b, k_b, v_b, fc1_w, fc1_b, fc2_w,
            wqkv, wo, qkvb, fc1w, fc1b, fc2w);
    }

    ln_bf16_kernel<<<MTOT / 4, 128>>>(x, ln1_w, ln1_b, xn);

    // fused QKV projection (2-stage; grid 24x32 = 768 CTAs)
    dim3 gqkv(QKVN / 64, MTOT / 128);
    gemm_mma<<<gqkv, 256, SMEM_GEMM>>>(xn, wqkv, qkvb, nullptr, qkv, DD, QKVN, DD,
                                       nullptr, nullptr, 4);

    // FA2 attention (128 queries/CTA, 2 CTAs/SM)
    dim3 gattn(NTOK / 128, HH, BB);
    attn_mma<<<gattn, 256>>>(qkv, qkv + (size_t)MTOT * DD, qkv + 2 * (size_t)MTOT * DD,
                             coords, ctxb);

    // O projection + residual1 (3-stage)
    dim3 gproj(DD / 64, MTOT / 128);
    gemm_mma3<<<gproj, 256, SMEM_GEMM3>>>(ctxb, wo, o_b, x1, nullptr, DD, DD, DD, x, gamma1, 1);

    ln_bf16_kernel<<<MTOT / 4, 128>>>(x1, ln2_w, ln2_b, xn2);

    // fc1 + fused SwiGLU (2-stage; grid 44x32 = 1408 CTAs)
    dim3 gfc1(HIDNP / 64, MTOT / 128);
    gemm_mma<<<gfc1, 256, SMEM_GEMM>>>(xn2, fc1w, fc1b, nullptr, hsb, HID2P, HIDNP, DD,
                                       nullptr, nullptr, 3);

    // fc2 + residual2 -> out (3-stage)
    gemm_mma3<<<gproj, 256, SMEM_GEMM3>>>(hsb, fc2w, fc2_b, out, nullptr, DD, DD, HID2P,
                                          x1, gamma2, 1);
}